// round 3
// baseline (speedup 1.0000x reference)
#include <cuda_runtime.h>
#include <cuda_bf16.h>
#include <mma.h>

using namespace nvcuda;

// Problem constants (fixed by the dataset instance)
static constexpr int T_TOK = 2048;
static constexpr int HS    = 2048;
static constexpr int IMZ   = 1408;
static constexpr int NE    = 32;

// Tiling
static constexpr int BM = 64;
static constexpr int BN = 128;
static constexpr int BK = 32;
static constexpr int NTHREADS = 256;      // 8 warps: 2 (m) x 4 (n)
static constexpr int LDA = BK + 8;        // 40 bf16 elems (80B row stride, 16B aligned)
static constexpr int LDB = BN + 8;        // 136 bf16 elems (272B row stride, 16B aligned)

// Scratch (static device allocations are allowed; cudaMalloc is not)
__device__ int   g_off[NE + 1];
__device__ float g_inter[(size_t)T_TOK * IMZ];

// ---------------------------------------------------------------------------
// Prefix sum of group sizes -> row offsets per expert
// ---------------------------------------------------------------------------
__global__ void prefix_kernel(const int* __restrict__ gs) {
    if (threadIdx.x == 0) {
        int acc = 0;
        g_off[0] = 0;
        for (int e = 0; e < NE; ++e) { acc += gs[e]; g_off[e + 1] = acc; }
    }
}

// Split fp32 into bf16 hi/lo pair (hi = rn(x), lo = rn(x - hi)).
// Error of the bf16x3 product scheme ~2^-16 relative; far below 1e-3.
__device__ __forceinline__ void split_store4(float4 v,
                                             __nv_bfloat16* __restrict__ hi,
                                             __nv_bfloat16* __restrict__ lo) {
    float f[4] = {v.x, v.y, v.z, v.w};
#pragma unroll
    for (int j = 0; j < 4; ++j) {
        __nv_bfloat16 h = __float2bfloat16_rn(f[j]);
        hi[j] = h;
        lo[j] = __float2bfloat16_rn(f[j] - __bfloat162float(h));
    }
}

// ---------------------------------------------------------------------------
// Kernel 1: inter = silu(H @ Wg[e]) * (H @ Wu[e])  per expert group
// Grid: (IMZ/BN, NE)
// ---------------------------------------------------------------------------
__global__ __launch_bounds__(NTHREADS)
void gateup_kernel(const float* __restrict__ H,    // [T, HS]
                   const float* __restrict__ Wg,   // [E, HS, IMZ]
                   const float* __restrict__ Wu)   // [E, HS, IMZ]
{
    // Shared memory: mainloop buffers aliased with the epilogue staging tile.
    // mainloop: A hi/lo 2*5120B + (G,U) hi/lo 4*8704B = 45056B
    // epilogue: 64 * 136 * 4B = 34816B
    __shared__ __align__(16) char smem[45056];
    __nv_bfloat16* sAhi = (__nv_bfloat16*)smem;              // [BM][LDA]
    __nv_bfloat16* sAlo = sAhi + BM * LDA;
    __nv_bfloat16* sGhi = (__nv_bfloat16*)(smem + 10240);    // [BK][LDB]
    __nv_bfloat16* sGlo = sGhi + BK * LDB;
    __nv_bfloat16* sUhi = sGlo + BK * LDB;
    __nv_bfloat16* sUlo = sUhi + BK * LDB;
    float* sStage = (float*)smem;                            // [BM][LDB]

    const int e   = blockIdx.y;
    const int n0  = blockIdx.x * BN;
    const int tid = threadIdx.x;
    const int wid = tid >> 5;
    const int warp_m = wid >> 2;   // 0..1 -> 32 rows each
    const int warp_n = wid & 3;    // 0..3 -> 32 cols each

    const int off0 = g_off[e];
    const int off1 = g_off[e + 1];

    const float* wg = Wg + (size_t)e * HS * IMZ + n0;
    const float* wu = Wu + (size_t)e * HS * IMZ + n0;

    for (int row_base = off0; row_base < off1; row_base += BM) {
        const int rows = min(BM, off1 - row_base);

        wmma::fragment<wmma::accumulator, 16, 16, 16, float> accg[2][2], accu[2][2];
#pragma unroll
        for (int m = 0; m < 2; ++m)
#pragma unroll
            for (int n = 0; n < 2; ++n) {
                wmma::fill_fragment(accg[m][n], 0.0f);
                wmma::fill_fragment(accu[m][n], 0.0f);
            }

        for (int k0 = 0; k0 < HS; k0 += BK) {
            // ---- global -> shared with on-the-fly bf16 hi/lo split ----
            // A tile: 64 x 32 fp32 = 512 float4, 2 per thread
#pragma unroll
            for (int i = 0; i < 2; ++i) {
                int id = tid + i * NTHREADS;
                int r  = id >> 3;
                int c  = (id & 7) * 4;
                float4 v = make_float4(0.f, 0.f, 0.f, 0.f);
                if (r < rows)
                    v = *(const float4*)(H + (size_t)(row_base + r) * HS + k0 + c);
                split_store4(v, sAhi + r * LDA + c, sAlo + r * LDA + c);
            }
            // G/U tiles: 32 x 128 fp32 each = 1024 float4, 4 per thread each
#pragma unroll
            for (int i = 0; i < 4; ++i) {
                int id = tid + i * NTHREADS;
                int r  = id >> 5;
                int c  = (id & 31) * 4;
                float4 vg = *(const float4*)(wg + (size_t)(k0 + r) * IMZ + c);
                float4 vu = *(const float4*)(wu + (size_t)(k0 + r) * IMZ + c);
                split_store4(vg, sGhi + r * LDB + c, sGlo + r * LDB + c);
                split_store4(vu, sUhi + r * LDB + c, sUlo + r * LDB + c);
            }
            __syncthreads();

            // ---- mma: 2 k-substeps of 16 ----
#pragma unroll
            for (int kk = 0; kk < 2; ++kk) {
                wmma::fragment<wmma::matrix_a, 16, 16, 16, __nv_bfloat16, wmma::row_major> ahi[2], alo[2];
#pragma unroll
                for (int m = 0; m < 2; ++m) {
                    const int ro = (warp_m * 32 + m * 16) * LDA + kk * 16;
                    wmma::load_matrix_sync(ahi[m], sAhi + ro, LDA);
                    wmma::load_matrix_sync(alo[m], sAlo + ro, LDA);
                }
                wmma::fragment<wmma::matrix_b, 16, 16, 16, __nv_bfloat16, wmma::row_major>
                    bghi[2], bglo[2], buhi[2], bulo[2];
#pragma unroll
                for (int n = 0; n < 2; ++n) {
                    const int co = (kk * 16) * LDB + warp_n * 32 + n * 16;
                    wmma::load_matrix_sync(bghi[n], sGhi + co, LDB);
                    wmma::load_matrix_sync(bglo[n], sGlo + co, LDB);
                    wmma::load_matrix_sync(buhi[n], sUhi + co, LDB);
                    wmma::load_matrix_sync(bulo[n], sUlo + co, LDB);
                }
#pragma unroll
                for (int m = 0; m < 2; ++m)
#pragma unroll
                    for (int n = 0; n < 2; ++n) {
                        wmma::mma_sync(accg[m][n], ahi[m], bghi[n], accg[m][n]);
                        wmma::mma_sync(accg[m][n], ahi[m], bglo[n], accg[m][n]);
                        wmma::mma_sync(accg[m][n], alo[m], bghi[n], accg[m][n]);
                        wmma::mma_sync(accu[m][n], ahi[m], buhi[n], accu[m][n]);
                        wmma::mma_sync(accu[m][n], ahi[m], bulo[n], accu[m][n]);
                        wmma::mma_sync(accu[m][n], alo[m], buhi[n], accu[m][n]);
                    }
            }
            __syncthreads();
        }

        // ---- epilogue: SwiGLU on fragments, stage via smem, predicated store ----
#pragma unroll
        for (int m = 0; m < 2; ++m)
#pragma unroll
            for (int n = 0; n < 2; ++n) {
#pragma unroll
                for (int i = 0; i < accg[m][n].num_elements; ++i) {
                    float g = accg[m][n].x[i];
                    float u = accu[m][n].x[i];
                    accg[m][n].x[i] = u * g / (1.0f + __expf(-g));
                }
                wmma::store_matrix_sync(
                    sStage + (warp_m * 32 + m * 16) * LDB + warp_n * 32 + n * 16,
                    accg[m][n], LDB, wmma::mem_row_major);
            }
        __syncthreads();
#pragma unroll
        for (int i = 0; i < 8; ++i) {
            int id = tid + i * NTHREADS;
            int r  = id >> 5;
            int c  = (id & 31) * 4;
            if (r < rows) {
                float4 v = *(const float4*)(sStage + r * LDB + c);
                *(float4*)(g_inter + (size_t)(row_base + r) * IMZ + n0 + c) = v;
            }
        }
        __syncthreads();
    }
}

// ---------------------------------------------------------------------------
// Kernel 2: out = inter @ Wd[e]  per expert group
// Grid: (HS/BN, NE)
// ---------------------------------------------------------------------------
__global__ __launch_bounds__(NTHREADS)
void down_kernel(const float* __restrict__ Wd,   // [E, IMZ, HS]
                 float* __restrict__ Out)        // [T, HS]
{
    // mainloop: A hi/lo 2*5120B + W hi/lo 2*8704B = 27648B; epilogue 34816B
    __shared__ __align__(16) char smem[34816];
    __nv_bfloat16* sAhi = (__nv_bfloat16*)smem;
    __nv_bfloat16* sAlo = sAhi + BM * LDA;
    __nv_bfloat16* sWhi = (__nv_bfloat16*)(smem + 10240);
    __nv_bfloat16* sWlo = sWhi + BK * LDB;
    float* sStage = (float*)smem;

    const int e   = blockIdx.y;
    const int n0  = blockIdx.x * BN;
    const int tid = threadIdx.x;
    const int wid = tid >> 5;
    const int warp_m = wid >> 2;
    const int warp_n = wid & 3;

    const int off0 = g_off[e];
    const int off1 = g_off[e + 1];

    const float* wd = Wd + (size_t)e * IMZ * HS + n0;

    for (int row_base = off0; row_base < off1; row_base += BM) {
        const int rows = min(BM, off1 - row_base);

        wmma::fragment<wmma::accumulator, 16, 16, 16, float> acc[2][2];
#pragma unroll
        for (int m = 0; m < 2; ++m)
#pragma unroll
            for (int n = 0; n < 2; ++n) wmma::fill_fragment(acc[m][n], 0.0f);

        for (int k0 = 0; k0 < IMZ; k0 += BK) {
#pragma unroll
            for (int i = 0; i < 2; ++i) {
                int id = tid + i * NTHREADS;
                int r  = id >> 3;
                int c  = (id & 7) * 4;
                float4 v = make_float4(0.f, 0.f, 0.f, 0.f);
                if (r < rows)
                    v = *(const float4*)(g_inter + (size_t)(row_base + r) * IMZ + k0 + c);
                split_store4(v, sAhi + r * LDA + c, sAlo + r * LDA + c);
            }
#pragma unroll
            for (int i = 0; i < 4; ++i) {
                int id = tid + i * NTHREADS;
                int r  = id >> 5;
                int c  = (id & 31) * 4;
                float4 vw = *(const float4*)(wd + (size_t)(k0 + r) * HS + c);
                split_store4(vw, sWhi + r * LDB + c, sWlo + r * LDB + c);
            }
            __syncthreads();

#pragma unroll
            for (int kk = 0; kk < 2; ++kk) {
                wmma::fragment<wmma::matrix_a, 16, 16, 16, __nv_bfloat16, wmma::row_major> ahi[2], alo[2];
#pragma unroll
                for (int m = 0; m < 2; ++m) {
                    const int ro = (warp_m * 32 + m * 16) * LDA + kk * 16;
                    wmma::load_matrix_sync(ahi[m], sAhi + ro, LDA);
                    wmma::load_matrix_sync(alo[m], sAlo + ro, LDA);
                }
                wmma::fragment<wmma::matrix_b, 16, 16, 16, __nv_bfloat16, wmma::row_major> bhi[2], blo[2];
#pragma unroll
                for (int n = 0; n < 2; ++n) {
                    const int co = (kk * 16) * LDB + warp_n * 32 + n * 16;
                    wmma::load_matrix_sync(bhi[n], sWhi + co, LDB);
                    wmma::load_matrix_sync(blo[n], sWlo + co, LDB);
                }
#pragma unroll
                for (int m = 0; m < 2; ++m)
#pragma unroll
                    for (int n = 0; n < 2; ++n) {
                        wmma::mma_sync(acc[m][n], ahi[m], bhi[n], acc[m][n]);
                        wmma::mma_sync(acc[m][n], ahi[m], blo[n], acc[m][n]);
                        wmma::mma_sync(acc[m][n], alo[m], bhi[n], acc[m][n]);
                    }
            }
            __syncthreads();
        }

#pragma unroll
        for (int m = 0; m < 2; ++m)
#pragma unroll
            for (int n = 0; n < 2; ++n)
                wmma::store_matrix_sync(
                    sStage + (warp_m * 32 + m * 16) * LDB + warp_n * 32 + n * 16,
                    acc[m][n], LDB, wmma::mem_row_major);
        __syncthreads();
#pragma unroll
        for (int i = 0; i < 8; ++i) {
            int id = tid + i * NTHREADS;
            int r  = id >> 5;
            int c  = (id & 31) * 4;
            if (r < rows) {
                float4 v = *(const float4*)(sStage + r * LDB + c);
                *(float4*)(Out + (size_t)(row_base + r) * HS + n0 + c) = v;
            }
        }
        __syncthreads();
    }
}

// ---------------------------------------------------------------------------
extern "C" void kernel_launch(void* const* d_in, const int* in_sizes, int n_in,
                              void* d_out, int out_size) {
    const float* H  = (const float*)d_in[0];   // hidden_states [T, HS]
    const float* Wg = (const float*)d_in[1];   // gate_kernel   [E, HS, IMZ]
    const float* Wu = (const float*)d_in[2];   // up_kernel     [E, HS, IMZ]
    const float* Wd = (const float*)d_in[3];   // down_kernel   [E, IMZ, HS]
    const int*   gs = (const int*)d_in[4];     // group_sizes   [E]
    float* Out = (float*)d_out;                // [T, HS]

    prefix_kernel<<<1, 32>>>(gs);
    gateup_kernel<<<dim3(IMZ / BN, NE), NTHREADS>>>(H, Wg, Wu);
    down_kernel<<<dim3(HS / BN, NE), NTHREADS>>>(Wd, Out);
}

// round 4
// speedup vs baseline: 1.4444x; 1.4444x over previous
#include <cuda_runtime.h>
#include <cuda_bf16.h>
#include <mma.h>

using namespace nvcuda;

// Problem constants (fixed by the dataset instance)
static constexpr int T_TOK = 2048;
static constexpr int HS    = 2048;
static constexpr int IMZ   = 1408;
static constexpr int NE    = 32;

// Tiling
static constexpr int BM = 64;
static constexpr int BN = 128;
static constexpr int BK = 32;
static constexpr int NTHREADS = 256;      // 8 warps: 2 (m) x 4 (n)
static constexpr int LDA = BK + 8;        // 40 bf16 elems (80B row stride, 16B aligned)
static constexpr int LDB = BN + 8;        // 136 bf16 elems (272B row stride, 16B aligned)

// Scratch (static device allocations are allowed; cudaMalloc is not)
__device__ int   g_off[NE + 1];
__device__ float g_inter[(size_t)T_TOK * IMZ];

// ---------------------------------------------------------------------------
// Prefix sum of group sizes -> row offsets per expert
// ---------------------------------------------------------------------------
__global__ void prefix_kernel(const int* __restrict__ gs) {
    if (threadIdx.x == 0) {
        int acc = 0;
        g_off[0] = 0;
        for (int e = 0; e < NE; ++e) { acc += gs[e]; g_off[e + 1] = acc; }
    }
}

// Split fp32 into bf16 hi/lo pair (hi = rn(x), lo = rn(x - hi)).
// Error of the bf16x3 product scheme ~2^-16 relative; far below 1e-3.
__device__ __forceinline__ void split_store4(float4 v,
                                             __nv_bfloat16* __restrict__ hi,
                                             __nv_bfloat16* __restrict__ lo) {
    float f[4] = {v.x, v.y, v.z, v.w};
#pragma unroll
    for (int j = 0; j < 4; ++j) {
        __nv_bfloat16 h = __float2bfloat16_rn(f[j]);
        hi[j] = h;
        lo[j] = __float2bfloat16_rn(f[j] - __bfloat162float(h));
    }
}

// ---------------------------------------------------------------------------
// Kernel 1: inter = silu(H @ Wg[e]) * (H @ Wu[e])  per expert group
// Grid: (IMZ/BN, NE)
// ---------------------------------------------------------------------------
__global__ __launch_bounds__(NTHREADS)
void gateup_kernel(const float* __restrict__ H,    // [T, HS]
                   const float* __restrict__ Wg,   // [E, HS, IMZ]
                   const float* __restrict__ Wu)   // [E, HS, IMZ]
{
    // Shared memory: mainloop buffers aliased with the epilogue staging tile.
    // mainloop: A hi/lo 2*5120B + (G,U) hi/lo 4*8704B = 45056B
    // epilogue: 64 * 136 * 4B = 34816B
    __shared__ __align__(16) char smem[45056];
    __nv_bfloat16* sAhi = (__nv_bfloat16*)smem;              // [BM][LDA]
    __nv_bfloat16* sAlo = sAhi + BM * LDA;
    __nv_bfloat16* sGhi = (__nv_bfloat16*)(smem + 10240);    // [BK][LDB]
    __nv_bfloat16* sGlo = sGhi + BK * LDB;
    __nv_bfloat16* sUhi = sGlo + BK * LDB;
    __nv_bfloat16* sUlo = sUhi + BK * LDB;
    float* sStage = (float*)smem;                            // [BM][LDB]

    const int e   = blockIdx.y;
    const int n0  = blockIdx.x * BN;
    const int tid = threadIdx.x;
    const int wid = tid >> 5;
    const int warp_m = wid >> 2;   // 0..1 -> 32 rows each
    const int warp_n = wid & 3;    // 0..3 -> 32 cols each

    const int off0 = g_off[e];
    const int off1 = g_off[e + 1];

    const float* wg = Wg + (size_t)e * HS * IMZ + n0;
    const float* wu = Wu + (size_t)e * HS * IMZ + n0;

    for (int row_base = off0; row_base < off1; row_base += BM) {
        const int rows = min(BM, off1 - row_base);

        wmma::fragment<wmma::accumulator, 16, 16, 16, float> accg[2][2], accu[2][2];
#pragma unroll
        for (int m = 0; m < 2; ++m)
#pragma unroll
            for (int n = 0; n < 2; ++n) {
                wmma::fill_fragment(accg[m][n], 0.0f);
                wmma::fill_fragment(accu[m][n], 0.0f);
            }

        for (int k0 = 0; k0 < HS; k0 += BK) {
            // ---- global -> shared with on-the-fly bf16 hi/lo split ----
            // A tile: 64 x 32 fp32 = 512 float4, 2 per thread
#pragma unroll
            for (int i = 0; i < 2; ++i) {
                int id = tid + i * NTHREADS;
                int r  = id >> 3;
                int c  = (id & 7) * 4;
                float4 v = make_float4(0.f, 0.f, 0.f, 0.f);
                if (r < rows)
                    v = *(const float4*)(H + (size_t)(row_base + r) * HS + k0 + c);
                split_store4(v, sAhi + r * LDA + c, sAlo + r * LDA + c);
            }
            // G/U tiles: 32 x 128 fp32 each = 1024 float4, 4 per thread each
#pragma unroll
            for (int i = 0; i < 4; ++i) {
                int id = tid + i * NTHREADS;
                int r  = id >> 5;
                int c  = (id & 31) * 4;
                float4 vg = *(const float4*)(wg + (size_t)(k0 + r) * IMZ + c);
                float4 vu = *(const float4*)(wu + (size_t)(k0 + r) * IMZ + c);
                split_store4(vg, sGhi + r * LDB + c, sGlo + r * LDB + c);
                split_store4(vu, sUhi + r * LDB + c, sUlo + r * LDB + c);
            }
            __syncthreads();

            // ---- mma: 2 k-substeps of 16 ----
#pragma unroll
            for (int kk = 0; kk < 2; ++kk) {
                wmma::fragment<wmma::matrix_a, 16, 16, 16, __nv_bfloat16, wmma::row_major> ahi[2], alo[2];
#pragma unroll
                for (int m = 0; m < 2; ++m) {
                    const int ro = (warp_m * 32 + m * 16) * LDA + kk * 16;
                    wmma::load_matrix_sync(ahi[m], sAhi + ro, LDA);
                    wmma::load_matrix_sync(alo[m], sAlo + ro, LDA);
                }
                wmma::fragment<wmma::matrix_b, 16, 16, 16, __nv_bfloat16, wmma::row_major>
                    bghi[2], bglo[2], buhi[2], bulo[2];
#pragma unroll
                for (int n = 0; n < 2; ++n) {
                    const int co = (kk * 16) * LDB + warp_n * 32 + n * 16;
                    wmma::load_matrix_sync(bghi[n], sGhi + co, LDB);
                    wmma::load_matrix_sync(bglo[n], sGlo + co, LDB);
                    wmma::load_matrix_sync(buhi[n], sUhi + co, LDB);
                    wmma::load_matrix_sync(bulo[n], sUlo + co, LDB);
                }
#pragma unroll
                for (int m = 0; m < 2; ++m)
#pragma unroll
                    for (int n = 0; n < 2; ++n) {
                        wmma::mma_sync(accg[m][n], ahi[m], bghi[n], accg[m][n]);
                        wmma::mma_sync(accg[m][n], ahi[m], bglo[n], accg[m][n]);
                        wmma::mma_sync(accg[m][n], alo[m], bghi[n], accg[m][n]);
                        wmma::mma_sync(accu[m][n], ahi[m], buhi[n], accu[m][n]);
                        wmma::mma_sync(accu[m][n], ahi[m], bulo[n], accu[m][n]);
                        wmma::mma_sync(accu[m][n], alo[m], buhi[n], accu[m][n]);
                    }
            }
            __syncthreads();
        }

        // ---- epilogue: SwiGLU on fragments, stage via smem, predicated store ----
#pragma unroll
        for (int m = 0; m < 2; ++m)
#pragma unroll
            for (int n = 0; n < 2; ++n) {
#pragma unroll
                for (int i = 0; i < accg[m][n].num_elements; ++i) {
                    float g = accg[m][n].x[i];
                    float u = accu[m][n].x[i];
                    accg[m][n].x[i] = u * g / (1.0f + __expf(-g));
                }
                wmma::store_matrix_sync(
                    sStage + (warp_m * 32 + m * 16) * LDB + warp_n * 32 + n * 16,
                    accg[m][n], LDB, wmma::mem_row_major);
            }
        __syncthreads();
#pragma unroll
        for (int i = 0; i < 8; ++i) {
            int id = tid + i * NTHREADS;
            int r  = id >> 5;
            int c  = (id & 31) * 4;
            if (r < rows) {
                float4 v = *(const float4*)(sStage + r * LDB + c);
                *(float4*)(g_inter + (size_t)(row_base + r) * IMZ + n0 + c) = v;
            }
        }
        __syncthreads();
    }
}

// ---------------------------------------------------------------------------
// Kernel 2: out = inter @ Wd[e]  per expert group
// Grid: (HS/BN, NE)
// ---------------------------------------------------------------------------
__global__ __launch_bounds__(NTHREADS)
void down_kernel(const float* __restrict__ Wd,   // [E, IMZ, HS]
                 float* __restrict__ Out)        // [T, HS]
{
    // mainloop: A hi/lo 2*5120B + W hi/lo 2*8704B = 27648B; epilogue 34816B
    __shared__ __align__(16) char smem[34816];
    __nv_bfloat16* sAhi = (__nv_bfloat16*)smem;
    __nv_bfloat16* sAlo = sAhi + BM * LDA;
    __nv_bfloat16* sWhi = (__nv_bfloat16*)(smem + 10240);
    __nv_bfloat16* sWlo = sWhi + BK * LDB;
    float* sStage = (float*)smem;

    const int e   = blockIdx.y;
    const int n0  = blockIdx.x * BN;
    const int tid = threadIdx.x;
    const int wid = tid >> 5;
    const int warp_m = wid >> 2;
    const int warp_n = wid & 3;

    const int off0 = g_off[e];
    const int off1 = g_off[e + 1];

    const float* wd = Wd + (size_t)e * IMZ * HS + n0;

    for (int row_base = off0; row_base < off1; row_base += BM) {
        const int rows = min(BM, off1 - row_base);

        wmma::fragment<wmma::accumulator, 16, 16, 16, float> acc[2][2];
#pragma unroll
        for (int m = 0; m < 2; ++m)
#pragma unroll
            for (int n = 0; n < 2; ++n) wmma::fill_fragment(acc[m][n], 0.0f);

        for (int k0 = 0; k0 < IMZ; k0 += BK) {
#pragma unroll
            for (int i = 0; i < 2; ++i) {
                int id = tid + i * NTHREADS;
                int r  = id >> 3;
                int c  = (id & 7) * 4;
                float4 v = make_float4(0.f, 0.f, 0.f, 0.f);
                if (r < rows)
                    v = *(const float4*)(g_inter + (size_t)(row_base + r) * IMZ + k0 + c);
                split_store4(v, sAhi + r * LDA + c, sAlo + r * LDA + c);
            }
#pragma unroll
            for (int i = 0; i < 4; ++i) {
                int id = tid + i * NTHREADS;
                int r  = id >> 5;
                int c  = (id & 31) * 4;
                float4 vw = *(const float4*)(wd + (size_t)(k0 + r) * HS + c);
                split_store4(vw, sWhi + r * LDB + c, sWlo + r * LDB + c);
            }
            __syncthreads();

#pragma unroll
            for (int kk = 0; kk < 2; ++kk) {
                wmma::fragment<wmma::matrix_a, 16, 16, 16, __nv_bfloat16, wmma::row_major> ahi[2], alo[2];
#pragma unroll
                for (int m = 0; m < 2; ++m) {
                    const int ro = (warp_m * 32 + m * 16) * LDA + kk * 16;
                    wmma::load_matrix_sync(ahi[m], sAhi + ro, LDA);
                    wmma::load_matrix_sync(alo[m], sAlo + ro, LDA);
                }
                wmma::fragment<wmma::matrix_b, 16, 16, 16, __nv_bfloat16, wmma::row_major> bhi[2], blo[2];
#pragma unroll
                for (int n = 0; n < 2; ++n) {
                    const int co = (kk * 16) * LDB + warp_n * 32 + n * 16;
                    wmma::load_matrix_sync(bhi[n], sWhi + co, LDB);
                    wmma::load_matrix_sync(blo[n], sWlo + co, LDB);
                }
#pragma unroll
                for (int m = 0; m < 2; ++m)
#pragma unroll
                    for (int n = 0; n < 2; ++n) {
                        wmma::mma_sync(acc[m][n], ahi[m], bhi[n], acc[m][n]);
                        wmma::mma_sync(acc[m][n], ahi[m], blo[n], acc[m][n]);
                        wmma::mma_sync(acc[m][n], alo[m], bhi[n], acc[m][n]);
                    }
            }
            __syncthreads();
        }

#pragma unroll
        for (int m = 0; m < 2; ++m)
#pragma unroll
            for (int n = 0; n < 2; ++n)
                wmma::store_matrix_sync(
                    sStage + (warp_m * 32 + m * 16) * LDB + warp_n * 32 + n * 16,
                    acc[m][n], LDB, wmma::mem_row_major);
        __syncthreads();
#pragma unroll
        for (int i = 0; i < 8; ++i) {
            int id = tid + i * NTHREADS;
            int r  = id >> 5;
            int c  = (id & 31) * 4;
            if (r < rows) {
                float4 v = *(const float4*)(sStage + r * LDB + c);
                *(float4*)(Out + (size_t)(row_base + r) * HS + n0 + c) = v;
            }
        }
        __syncthreads();
    }
}

// ---------------------------------------------------------------------------
extern "C" void kernel_launch(void* const* d_in, const int* in_sizes, int n_in,
                              void* d_out, int out_size) {
    const float* H  = (const float*)d_in[0];   // hidden_states [T, HS]
    const float* Wg = (const float*)d_in[1];   // gate_kernel   [E, HS, IMZ]
    const float* Wu = (const float*)d_in[2];   // up_kernel     [E, HS, IMZ]
    const float* Wd = (const float*)d_in[3];   // down_kernel   [E, IMZ, HS]
    const int*   gs = (const int*)d_in[4];     // group_sizes   [E]
    float* Out = (float*)d_out;                // [T, HS]

    prefix_kernel<<<1, 32>>>(gs);
    gateup_kernel<<<dim3(IMZ / BN, NE), NTHREADS>>>(H, Wg, Wu);
    down_kernel<<<dim3(HS / BN, NE), NTHREADS>>>(Wd, Out);
}

// round 5
// speedup vs baseline: 1.6201x; 1.1216x over previous
#include <cuda_runtime.h>
#include <cuda_bf16.h>
#include <mma.h>

using namespace nvcuda;

// Problem constants (fixed by the dataset instance)
static constexpr int T_TOK = 2048;
static constexpr int HS    = 2048;
static constexpr int IMZ   = 1408;
static constexpr int NE    = 32;

// Tiling
static constexpr int BM = 64;
static constexpr int BN = 128;
static constexpr int BK = 32;
static constexpr int NTHREADS = 256;      // 8 warps: 2 (m) x 4 (n)
static constexpr int LDA = BK + 8;        // 40 bf16 elems (80B rows, 8B-aligned cols)
static constexpr int LDB = BN + 8;        // 136 bf16 elems (272B rows, 8B-aligned cols)

// Scratch (static device allocations are allowed; cudaMalloc is not)
__device__ float g_inter[(size_t)T_TOK * IMZ];

// ---------------------------------------------------------------------------
// fp32 -> bf16 hi/lo split, packed as uint2 (4 bf16 = 8B) for STS.64 stores.
// hi = rn(x), lo = rn(x - hi). bf16x3 product error ~2^-16 rel.
// ---------------------------------------------------------------------------
__device__ __forceinline__ void split4(float4 v, uint2& hi, uint2& lo) {
    __nv_bfloat16 hx = __float2bfloat16_rn(v.x);
    __nv_bfloat16 hy = __float2bfloat16_rn(v.y);
    __nv_bfloat16 hz = __float2bfloat16_rn(v.z);
    __nv_bfloat16 hw = __float2bfloat16_rn(v.w);
    union { __nv_bfloat162 b2[2]; uint2 u; } H, L;
    H.b2[0] = __halves2bfloat162(hx, hy);
    H.b2[1] = __halves2bfloat162(hz, hw);
    L.b2[0] = __floats2bfloat162_rn(v.x - __bfloat162float(hx),
                                    v.y - __bfloat162float(hy));
    L.b2[1] = __floats2bfloat162_rn(v.z - __bfloat162float(hz),
                                    v.w - __bfloat162float(hw));
    hi = H.u;
    lo = L.u;
}

// Per-block expert offsets via warp shfl inclusive scan of group_sizes.
__device__ __forceinline__ void expert_offsets(const int* __restrict__ gs,
                                               int e, int tid,
                                               int* __restrict__ s_off) {
    if (tid < 32) {
        int g = (tid < NE) ? gs[tid] : 0;
        int v = g;
#pragma unroll
        for (int d = 1; d < 32; d <<= 1) {
            int t = __shfl_up_sync(0xffffffffu, v, d);
            if (tid >= d) v += t;
        }
        if (tid == e) { s_off[1] = v; s_off[0] = v - g; }
    }
}

// ---------------------------------------------------------------------------
// Kernel 1: inter = silu(H @ Wg[e]) * (H @ Wu[e])  per expert group
// Grid: (IMZ/BN, NE).  Register-prefetch pipelined mainloop.
// ---------------------------------------------------------------------------
__global__ __launch_bounds__(NTHREADS)
void gateup_kernel(const float* __restrict__ H,    // [T, HS]
                   const float* __restrict__ Wg,   // [E, HS, IMZ]
                   const float* __restrict__ Wu,   // [E, HS, IMZ]
                   const int* __restrict__ gs)
{
    // mainloop: A hi/lo 2*5120B + (G,U) hi/lo 4*8704B = 45056B
    // epilogue stage (aliased): 64 * 136 * 4B = 34816B
    __shared__ __align__(16) char smem[45056];
    __shared__ int s_off[2];
    __nv_bfloat16* sAhi = (__nv_bfloat16*)smem;              // [BM][LDA]
    __nv_bfloat16* sAlo = sAhi + BM * LDA;
    __nv_bfloat16* sGhi = (__nv_bfloat16*)(smem + 10240);    // [BK][LDB]
    __nv_bfloat16* sGlo = sGhi + BK * LDB;
    __nv_bfloat16* sUhi = sGlo + BK * LDB;
    __nv_bfloat16* sUlo = sUhi + BK * LDB;
    float* sStage = (float*)smem;                            // [BM][LDB]

    const int e   = blockIdx.y;
    const int n0  = blockIdx.x * BN;
    const int tid = threadIdx.x;
    const int wid = tid >> 5;
    const int warp_m = wid >> 2;   // 0..1 -> 32 rows each
    const int warp_n = wid & 3;    // 0..3 -> 32 cols each

    expert_offsets(gs, e, tid, s_off);
    __syncthreads();
    const int off0 = s_off[0];
    const int off1 = s_off[1];

    // Per-thread fixed load coordinates
    const int rA = tid >> 3;            // + 32*i
    const int cA = (tid & 7) * 4;
    const int rB = tid >> 5;            // + 8*i
    const int cB = (tid & 31) * 4;

    const float* wg = Wg + (size_t)e * HS * IMZ + n0;
    const float* wu = Wu + (size_t)e * HS * IMZ + n0;

    for (int row_base = off0; row_base < off1; row_base += BM) {
        const int rows = min(BM, off1 - row_base);

        wmma::fragment<wmma::accumulator, 16, 16, 16, float> accg[2][2], accu[2][2];
#pragma unroll
        for (int m = 0; m < 2; ++m)
#pragma unroll
            for (int n = 0; n < 2; ++n) {
                wmma::fill_fragment(accg[m][n], 0.0f);
                wmma::fill_fragment(accu[m][n], 0.0f);
            }

        float4 ra[2], rg[4], ru[4];
        // ---- prologue: load k-tile 0 into registers ----
#pragma unroll
        for (int i = 0; i < 2; ++i)
            ra[i] = (rA + 32 * i < rows)
                  ? *(const float4*)(H + (size_t)(row_base + rA + 32 * i) * HS + cA)
                  : make_float4(0.f, 0.f, 0.f, 0.f);
#pragma unroll
        for (int i = 0; i < 4; ++i) {
            rg[i] = *(const float4*)(wg + (size_t)(rB + 8 * i) * IMZ + cB);
            ru[i] = *(const float4*)(wu + (size_t)(rB + 8 * i) * IMZ + cB);
        }

        for (int k0 = 0; k0 < HS; k0 += BK) {
            // ---- split+store current registers to shared ----
#pragma unroll
            for (int i = 0; i < 2; ++i) {
                uint2 hi, lo;
                split4(ra[i], hi, lo);
                *(uint2*)(sAhi + (rA + 32 * i) * LDA + cA) = hi;
                *(uint2*)(sAlo + (rA + 32 * i) * LDA + cA) = lo;
            }
#pragma unroll
            for (int i = 0; i < 4; ++i) {
                uint2 hi, lo;
                split4(rg[i], hi, lo);
                *(uint2*)(sGhi + (rB + 8 * i) * LDB + cB) = hi;
                *(uint2*)(sGlo + (rB + 8 * i) * LDB + cB) = lo;
                split4(ru[i], hi, lo);
                *(uint2*)(sUhi + (rB + 8 * i) * LDB + cB) = hi;
                *(uint2*)(sUlo + (rB + 8 * i) * LDB + cB) = lo;
            }
            __syncthreads();

            // ---- prefetch next k-tile into registers (overlaps MMA) ----
            const int kn = k0 + BK;
            if (kn < HS) {
#pragma unroll
                for (int i = 0; i < 2; ++i)
                    ra[i] = (rA + 32 * i < rows)
                          ? *(const float4*)(H + (size_t)(row_base + rA + 32 * i) * HS + kn + cA)
                          : make_float4(0.f, 0.f, 0.f, 0.f);
#pragma unroll
                for (int i = 0; i < 4; ++i) {
                    rg[i] = *(const float4*)(wg + (size_t)(kn + rB + 8 * i) * IMZ + cB);
                    ru[i] = *(const float4*)(wu + (size_t)(kn + rB + 8 * i) * IMZ + cB);
                }
            }

            // ---- mma: 2 k-substeps of 16 ----
#pragma unroll
            for (int kk = 0; kk < 2; ++kk) {
                wmma::fragment<wmma::matrix_a, 16, 16, 16, __nv_bfloat16, wmma::row_major> ahi[2], alo[2];
#pragma unroll
                for (int m = 0; m < 2; ++m) {
                    const int ro = (warp_m * 32 + m * 16) * LDA + kk * 16;
                    wmma::load_matrix_sync(ahi[m], sAhi + ro, LDA);
                    wmma::load_matrix_sync(alo[m], sAlo + ro, LDA);
                }
#pragma unroll
                for (int n = 0; n < 2; ++n) {
                    const int co = (kk * 16) * LDB + warp_n * 32 + n * 16;
                    wmma::fragment<wmma::matrix_b, 16, 16, 16, __nv_bfloat16, wmma::row_major>
                        bghi, bglo, buhi, bulo;
                    wmma::load_matrix_sync(bghi, sGhi + co, LDB);
                    wmma::load_matrix_sync(bglo, sGlo + co, LDB);
                    wmma::load_matrix_sync(buhi, sUhi + co, LDB);
                    wmma::load_matrix_sync(bulo, sUlo + co, LDB);
#pragma unroll
                    for (int m = 0; m < 2; ++m) {
                        wmma::mma_sync(accg[m][n], ahi[m], bghi, accg[m][n]);
                        wmma::mma_sync(accg[m][n], ahi[m], bglo, accg[m][n]);
                        wmma::mma_sync(accg[m][n], alo[m], bghi, accg[m][n]);
                        wmma::mma_sync(accu[m][n], ahi[m], buhi, accu[m][n]);
                        wmma::mma_sync(accu[m][n], ahi[m], bulo, accu[m][n]);
                        wmma::mma_sync(accu[m][n], alo[m], buhi, accu[m][n]);
                    }
                }
            }
            __syncthreads();
        }

        // ---- epilogue: SwiGLU on fragments, stage via smem, predicated store ----
#pragma unroll
        for (int m = 0; m < 2; ++m)
#pragma unroll
            for (int n = 0; n < 2; ++n) {
#pragma unroll
                for (int i = 0; i < accg[m][n].num_elements; ++i) {
                    float g = accg[m][n].x[i];
                    float u = accu[m][n].x[i];
                    accg[m][n].x[i] = u * g / (1.0f + __expf(-g));
                }
                wmma::store_matrix_sync(
                    sStage + (warp_m * 32 + m * 16) * LDB + warp_n * 32 + n * 16,
                    accg[m][n], LDB, wmma::mem_row_major);
            }
        __syncthreads();
#pragma unroll
        for (int i = 0; i < 8; ++i) {
            int id = tid + i * NTHREADS;
            int r  = id >> 5;
            int c  = (id & 31) * 4;
            if (r < rows) {
                float4 v = *(const float4*)(sStage + r * LDB + c);
                *(float4*)(g_inter + (size_t)(row_base + r) * IMZ + n0 + c) = v;
            }
        }
        __syncthreads();
    }
}

// ---------------------------------------------------------------------------
// Kernel 2: out = inter @ Wd[e]  per expert group
// Grid: (HS/BN, NE).  Register-prefetch pipelined mainloop.
// ---------------------------------------------------------------------------
__global__ __launch_bounds__(NTHREADS)
void down_kernel(const float* __restrict__ Wd,   // [E, IMZ, HS]
                 float* __restrict__ Out,        // [T, HS]
                 const int* __restrict__ gs)
{
    // mainloop: A hi/lo 2*5120B + W hi/lo 2*8704B = 27648B; epilogue 34816B
    __shared__ __align__(16) char smem[34816];
    __shared__ int s_off[2];
    __nv_bfloat16* sAhi = (__nv_bfloat16*)smem;
    __nv_bfloat16* sAlo = sAhi + BM * LDA;
    __nv_bfloat16* sWhi = (__nv_bfloat16*)(smem + 10240);
    __nv_bfloat16* sWlo = sWhi + BK * LDB;
    float* sStage = (float*)smem;

    const int e   = blockIdx.y;
    const int n0  = blockIdx.x * BN;
    const int tid = threadIdx.x;
    const int wid = tid >> 5;
    const int warp_m = wid >> 2;
    const int warp_n = wid & 3;

    expert_offsets(gs, e, tid, s_off);
    __syncthreads();
    const int off0 = s_off[0];
    const int off1 = s_off[1];

    const int rA = tid >> 3;
    const int cA = (tid & 7) * 4;
    const int rB = tid >> 5;
    const int cB = (tid & 31) * 4;

    const float* wd = Wd + (size_t)e * IMZ * HS + n0;

    for (int row_base = off0; row_base < off1; row_base += BM) {
        const int rows = min(BM, off1 - row_base);

        wmma::fragment<wmma::accumulator, 16, 16, 16, float> acc[2][2];
#pragma unroll
        for (int m = 0; m < 2; ++m)
#pragma unroll
            for (int n = 0; n < 2; ++n) wmma::fill_fragment(acc[m][n], 0.0f);

        float4 ra[2], rw[4];
#pragma unroll
        for (int i = 0; i < 2; ++i)
            ra[i] = (rA + 32 * i < rows)
                  ? *(const float4*)(g_inter + (size_t)(row_base + rA + 32 * i) * IMZ + cA)
                  : make_float4(0.f, 0.f, 0.f, 0.f);
#pragma unroll
        for (int i = 0; i < 4; ++i)
            rw[i] = *(const float4*)(wd + (size_t)(rB + 8 * i) * HS + cB);

        for (int k0 = 0; k0 < IMZ; k0 += BK) {
#pragma unroll
            for (int i = 0; i < 2; ++i) {
                uint2 hi, lo;
                split4(ra[i], hi, lo);
                *(uint2*)(sAhi + (rA + 32 * i) * LDA + cA) = hi;
                *(uint2*)(sAlo + (rA + 32 * i) * LDA + cA) = lo;
            }
#pragma unroll
            for (int i = 0; i < 4; ++i) {
                uint2 hi, lo;
                split4(rw[i], hi, lo);
                *(uint2*)(sWhi + (rB + 8 * i) * LDB + cB) = hi;
                *(uint2*)(sWlo + (rB + 8 * i) * LDB + cB) = lo;
            }
            __syncthreads();

            const int kn = k0 + BK;
            if (kn < IMZ) {
#pragma unroll
                for (int i = 0; i < 2; ++i)
                    ra[i] = (rA + 32 * i < rows)
                          ? *(const float4*)(g_inter + (size_t)(row_base + rA + 32 * i) * IMZ + kn + cA)
                          : make_float4(0.f, 0.f, 0.f, 0.f);
#pragma unroll
                for (int i = 0; i < 4; ++i)
                    rw[i] = *(const float4*)(wd + (size_t)(kn + rB + 8 * i) * HS + cB);
            }

#pragma unroll
            for (int kk = 0; kk < 2; ++kk) {
                wmma::fragment<wmma::matrix_a, 16, 16, 16, __nv_bfloat16, wmma::row_major> ahi[2], alo[2];
#pragma unroll
                for (int m = 0; m < 2; ++m) {
                    const int ro = (warp_m * 32 + m * 16) * LDA + kk * 16;
                    wmma::load_matrix_sync(ahi[m], sAhi + ro, LDA);
                    wmma::load_matrix_sync(alo[m], sAlo + ro, LDA);
                }
#pragma unroll
                for (int n = 0; n < 2; ++n) {
                    const int co = (kk * 16) * LDB + warp_n * 32 + n * 16;
                    wmma::fragment<wmma::matrix_b, 16, 16, 16, __nv_bfloat16, wmma::row_major> bhi, blo;
                    wmma::load_matrix_sync(bhi, sWhi + co, LDB);
                    wmma::load_matrix_sync(blo, sWlo + co, LDB);
#pragma unroll
                    for (int m = 0; m < 2; ++m) {
                        wmma::mma_sync(acc[m][n], ahi[m], bhi, acc[m][n]);
                        wmma::mma_sync(acc[m][n], ahi[m], blo, acc[m][n]);
                        wmma::mma_sync(acc[m][n], alo[m], bhi, acc[m][n]);
                    }
                }
            }
            __syncthreads();
        }

#pragma unroll
        for (int m = 0; m < 2; ++m)
#pragma unroll
            for (int n = 0; n < 2; ++n)
                wmma::store_matrix_sync(
                    sStage + (warp_m * 32 + m * 16) * LDB + warp_n * 32 + n * 16,
                    acc[m][n], LDB, wmma::mem_row_major);
        __syncthreads();
#pragma unroll
        for (int i = 0; i < 8; ++i) {
            int id = tid + i * NTHREADS;
            int r  = id >> 5;
            int c  = (id & 31) * 4;
            if (r < rows) {
                float4 v = *(const float4*)(sStage + r * LDB + c);
                *(float4*)(Out + (size_t)(row_base + r) * HS + n0 + c) = v;
            }
        }
        __syncthreads();
    }
}

// ---------------------------------------------------------------------------
extern "C" void kernel_launch(void* const* d_in, const int* in_sizes, int n_in,
                              void* d_out, int out_size) {
    const float* H  = (const float*)d_in[0];   // hidden_states [T, HS]
    const float* Wg = (const float*)d_in[1];   // gate_kernel   [E, HS, IMZ]
    const float* Wu = (const float*)d_in[2];   // up_kernel     [E, HS, IMZ]
    const float* Wd = (const float*)d_in[3];   // down_kernel   [E, IMZ, HS]
    const int*   gs = (const int*)d_in[4];     // group_sizes   [E]
    float* Out = (float*)d_out;                // [T, HS]

    gateup_kernel<<<dim3(IMZ / BN, NE), NTHREADS>>>(H, Wg, Wu, gs);
    down_kernel<<<dim3(HS / BN, NE), NTHREADS>>>(Wd, Out, gs);
}